// round 5
// baseline (speedup 1.0000x reference)
#include <cuda_runtime.h>
#include <cstdint>

#define N_EDGES 250000
#define N_RBF   10
#define FEAT    144
#define P_TOTAL 4864
#define TILE_E  32
#define THREADS 256
#define VSTRIDE 20                      // Rt w-row stride (16 used + 4 pad)
#define RSLICE  (16 * VSTRIDE)          // 320 floats per r-slice
#define RBUF    (N_RBF * RSLICE)        // 3200 floats per buffer
#define YS_STR  40                      // padded Ys per-edge stride
#define TMP_ESTR 88                     // tmp per-edge stride (conflict-free halves)
#define TMP_WARP (4 * TMP_ESTR)         // 352 floats per warp

__constant__ float cg_c[1225];

// ---------------------------------------------------------------------------
// One path. tmp phase: lane (m,eh) computes tmp[v=m][o] for its 2 edges
// (leA=2eh, leB=2eh+1) and publishes to warp scratch. W/apply phase: lane
// handles w=m for ALL 4 warp edges but only its v-half (eh): Rt LDS count
// halved; partial outputs later combined via shfl.xor(16).
// ---------------------------------------------------------------------------
template<int IO, int II, int LF, int CGOFF>
__device__ __forceinline__ void do_path(
    const float (&FAr)[9], const float (&FBr)[9],
    const float* __restrict__ Ys_p,     // [TILE_E][YS_STR] padded
    const float* __restrict__ Rt,       // [10][16][VSTRIDE]
    float* __restrict__ tmp_w,          // this warp's scratch
    const float (&rad)[4][N_RBF],
    int m, int eh, int lA, int lB, int leA,
    float (&outp)[4][5])
{
    constexpr int DOUT = 2 * IO + 1;
    constexpr int DI   = 2 * II + 1;
    constexpr int DF   = 2 * LF + 1;
    constexpr int FB0  = (II == 0) ? 0 : ((II == 1) ? 1 : 4);
    constexpr int YB   = (LF == 0) ? 0 : (LF == 1) ? 4 : (LF == 2) ? 12
                       : (LF == 3) ? 20 : 28;
    const float NORM =
        (DF == 1) ? 1.0f :
        (DF == 3) ? 0.57735026918962576f :
        (DF == 5) ? 0.44721359549995794f :
        (DF == 7) ? 0.37796447300922723f :
                    0.33333333333333333f;

    // ---- vectorized Ys loads (padded, 16B aligned blocks) ----
    float yA[DF], yB[DF];
    {
        const float* pa = Ys_p + lA * YS_STR + YB;
        const float* pb = Ys_p + lB * YS_STR + YB;
        if constexpr (DF == 1) {
            yA[0] = pa[0]; yB[0] = pb[0];
        } else if constexpr (DF == 3) {
            float4 qa = *(const float4*)pa, qb = *(const float4*)pb;
            yA[0]=qa.x; yA[1]=qa.y; yA[2]=qa.z;
            yB[0]=qb.x; yB[1]=qb.y; yB[2]=qb.z;
        } else if constexpr (DF == 5) {
            float4 qa = *(const float4*)pa, qb = *(const float4*)pb;
            yA[0]=qa.x; yA[1]=qa.y; yA[2]=qa.z; yA[3]=qa.w; yA[4]=pa[4];
            yB[0]=qb.x; yB[1]=qb.y; yB[2]=qb.z; yB[3]=qb.w; yB[4]=pb[4];
        } else if constexpr (DF == 7) {
            float4 qa0 = *(const float4*)pa, qa1 = *(const float4*)(pa + 4);
            float4 qb0 = *(const float4*)pb, qb1 = *(const float4*)(pb + 4);
            yA[0]=qa0.x; yA[1]=qa0.y; yA[2]=qa0.z; yA[3]=qa0.w;
            yA[4]=qa1.x; yA[5]=qa1.y; yA[6]=qa1.z;
            yB[0]=qb0.x; yB[1]=qb0.y; yB[2]=qb0.z; yB[3]=qb0.w;
            yB[4]=qb1.x; yB[5]=qb1.y; yB[6]=qb1.z;
        } else {
            float4 qa0 = *(const float4*)pa, qa1 = *(const float4*)(pa + 4);
            float4 qb0 = *(const float4*)pb, qb1 = *(const float4*)(pb + 4);
            yA[0]=qa0.x; yA[1]=qa0.y; yA[2]=qa0.z; yA[3]=qa0.w;
            yA[4]=qa1.x; yA[5]=qa1.y; yA[6]=qa1.z; yA[7]=qa1.w; yA[8]=pa[8];
            yB[0]=qb0.x; yB[1]=qb0.y; yB[2]=qb0.z; yB[3]=qb0.w;
            yB[4]=qb1.x; yB[5]=qb1.y; yB[6]=qb1.z; yB[7]=qb1.w; yB[8]=pb[8];
        }
    }

    // ---- tmp[v=m][o] for this lane's 2 edges ----
    float tA[DOUT], tB[DOUT];
#pragma unroll
    for (int o = 0; o < DOUT; o++) { tA[o] = 0.f; tB[o] = 0.f; }

#pragma unroll
    for (int f = 0; f < DF; f++) {
#pragma unroll
        for (int o = 0; o < DOUT; o++) {
            float gA = 0.f, gB = 0.f;
#pragma unroll
            for (int i = 0; i < DI; i++) {
                float c = cg_c[CGOFF + (o * DI + i) * DF + f];  // LDCU uniform
                gA += FAr[FB0 + i] * c;
                gB += FBr[FB0 + i] * c;
            }
            tA[o] += yA[f] * gA;
            tB[o] += yB[f] * gB;
        }
    }

    // ---- publish tmp to warp scratch (conflict-free: stride 88) ----
    __syncwarp();
#pragma unroll
    for (int o = 0; o < DOUT; o++) {
        tmp_w[ leA      * TMP_ESTR + o * 16 + m] = tA[o] * NORM;
        tmp_w[(leA + 1) * TMP_ESTR + o * 16 + m] = tB[o] * NORM;
    }
    __syncwarp();

    // ---- v-split W + apply: lane covers 4 edges, its v-half only ----
    const float* row = Rt + m * VSTRIDE;
#pragma unroll
    for (int g = 0; g < 2; g++) {
        const int v0 = (2 * eh + g) * 4;
        float w4[4][4];
#pragma unroll
        for (int j = 0; j < 4; j++)
#pragma unroll
            for (int k = 0; k < 4; k++) w4[j][k] = 0.f;

#pragma unroll
        for (int r = 0; r < N_RBF; r++) {
            float4 q = *(const float4*)(row + r * RSLICE + v0);
#pragma unroll
            for (int j = 0; j < 4; j++) {
                w4[j][0] += rad[j][r] * q.x;
                w4[j][1] += rad[j][r] * q.y;
                w4[j][2] += rad[j][r] * q.z;
                w4[j][3] += rad[j][r] * q.w;
            }
        }
#pragma unroll
        for (int j = 0; j < 4; j++) {
#pragma unroll
            for (int o = 0; o < DOUT; o++) {
                float4 t = *(const float4*)(tmp_w + j * TMP_ESTR + o * 16 + v0);
                outp[j][o] += w4[j][0] * t.x + w4[j][1] * t.y
                            + w4[j][2] * t.z + w4[j][3] * t.w;
            }
        }
    }
}

// ---------------------------------------------------------------------------
__global__ void __launch_bounds__(THREADS, 2)
conv_kernel(const float* __restrict__ features,
            const float* __restrict__ R,
            const float* __restrict__ Ys,
            const float* __restrict__ radii,
            const float* __restrict__ n_norm,
            const int*   __restrict__ map_a,
            const int*   __restrict__ map_b,
            float* __restrict__ out)
{
    __shared__ __align__(16) float Rt[2][RBUF];          // 25.6 kB
    __shared__ __align__(16) float tmp_s[8 * TMP_WARP];  // 11.3 kB
    __shared__ __align__(16) float Ys_p[TILE_E * YS_STR];//  5.1 kB

    const int tid  = threadIdx.x;
    const int warp = tid >> 5;
    const int lane = tid & 31;
    const int m    = lane & 15;
    const int eh   = lane >> 4;
    const int e0   = blockIdx.x * TILE_E;
    const int leA  = eh * 2;
    const int lA   = warp * 4 + leA;
    const int lB   = lA + 1;
    float* tmp_w   = tmp_s + warp * TMP_WARP;

    const uint32_t rt_sm0 = (uint32_t)__cvta_generic_to_shared(&Rt[0][0]);
    const uint32_t rt_sm1 = (uint32_t)__cvta_generic_to_shared(&Rt[1][0]);

    // cp.async staging of path P's R block (2560 floats = 640 16B chunks)
#define ISSUE(P, BUF)                                                          \
    do {                                                                       \
        uint32_t base = (BUF) ? rt_sm1 : rt_sm0;                               \
        _Pragma("unroll")                                                      \
        for (int c = tid; c < 640; c += THREADS) {                             \
            int k = c >> 6, w = (c >> 2) & 15, q = c & 3;                      \
            const float* src = R + (size_t)k * P_TOTAL + (P) * 256             \
                                 + w * 16 + q * 4;                             \
            uint32_t dst = base + (uint32_t)(((k * 16 + w) * VSTRIDE + q * 4)  \
                                             * 4);                             \
            asm volatile("cp.async.cg.shared.global [%0], [%1], 16;"           \
                         :: "r"(dst), "l"(src));                               \
        }                                                                      \
    } while (0)

#define COMMITG() asm volatile("cp.async.commit_group;" ::: "memory")

    ISSUE(0, 0);
    COMMITG();

    // ---- stage padded Ys ----
    for (int idx = tid; idx < TILE_E * 25; idx += THREADS) {
        int le = idx / 25, f = idx - le * 25;
        int e  = e0 + le;
        int off = (f < 1) ? f : (f < 4) ? 3 + f : (f < 9) ? 8 + f
                : (f < 16) ? 11 + f : 12 + f;
        Ys_p[le * YS_STR + off] = (e < N_EDGES) ? Ys[(size_t)e * 25 + f] : 0.f;
    }

    // ---- per-lane bindings ----
    const int eA = e0 + lA, eB = e0 + lB;
    const bool vA = (eA < N_EDGES), vB = (eB < N_EDGES);
    const int eAc = vA ? eA : 0, eBc = vB ? eB : 0;

    float FAr[9], FBr[9];
    {
        const float* fA = features + (size_t)map_b[eAc] * FEAT;
        const float* fB = features + (size_t)map_b[eBc] * FEAT;
        FAr[0] = fA[m];                 FBr[0] = fB[m];
#pragma unroll
        for (int i = 0; i < 3; i++) { FAr[1 + i] = fA[16 + m * 3 + i];
                                      FBr[1 + i] = fB[16 + m * 3 + i]; }
#pragma unroll
        for (int i = 0; i < 5; i++) { FAr[4 + i] = fA[64 + m * 5 + i];
                                      FBr[4 + i] = fB[64 + m * 5 + i]; }
    }

    // all 4 warp edges' radial coefficients (for v-split W phase)
    float rad[4][N_RBF];
#pragma unroll
    for (int j = 0; j < 4; j++) {
        int e = e0 + warp * 4 + j;
        bool v = (e < N_EDGES);
        int ec = v ? e : 0;
#pragma unroll
        for (int r = 0; r < N_RBF; r++)
            rad[j][r] = v ? radii[(size_t)ec * N_RBF + r] : 0.f;
    }

    const int   aA  = map_a[eAc];
    const int   aB  = map_a[eBc];
    const float nnA = vA ? n_norm[aA] : 0.f;
    const float nnB = vB ? n_norm[aB] : 0.f;

    float outp[4][5];
#pragma unroll
    for (int j = 0; j < 4; j++)
#pragma unroll
        for (int o = 0; o < 5; o++) outp[j][o] = 0.f;

    // STEP P: wait for path P's cp.async, sync (also frees buf[(P+1)&1]),
    // kick off path P+1's staging, compute path P.
#define STEP(P, IO, II, LF, CGOFF)                                             \
    do {                                                                       \
        asm volatile("cp.async.wait_group 0;" ::: "memory");                   \
        __syncthreads();                                                       \
        if ((P) < 18) { ISSUE((P) + 1, ((P) + 1) & 1); COMMITG(); }            \
        do_path<IO, II, LF, CGOFF>(FAr, FBr, Ys_p, Rt[(P) & 1], tmp_w,         \
                                   rad, m, eh, lA, lB, leA, outp);             \
    } while (0)

#define REDUCE(DOUT)                                                           \
    do {                                                                       \
        _Pragma("unroll")                                                      \
        for (int j = 0; j < 4; j++)                                            \
            _Pragma("unroll")                                                  \
            for (int o = 0; o < (DOUT); o++)                                   \
                outp[j][o] += __shfl_xor_sync(0xffffffffu, outp[j][o], 16);    \
    } while (0)

#define CLEAR()                                                                \
    do {                                                                       \
        _Pragma("unroll")                                                      \
        for (int j = 0; j < 4; j++)                                            \
            _Pragma("unroll")                                                  \
            for (int o = 0; o < 5; o++) outp[j][o] = 0.f;                      \
    } while (0)

    // ---------------- io = 0 (DOUT = 1, out offset 0) -----------------------
    STEP(0, 0, 0, 0, 0);
    STEP(1, 0, 1, 1, 1);
    STEP(2, 0, 2, 2, 10);
    REDUCE(1);
    if (vA) atomicAdd(&out[(size_t)aA * FEAT + m], nnA * outp[leA][0]);
    if (vB) atomicAdd(&out[(size_t)aB * FEAT + m], nnB * outp[leA + 1][0]);
    CLEAR();

    // ---------------- io = 1 (DOUT = 3, out offset 16) ----------------------
    STEP(3, 1, 0, 1, 35);
    STEP(4, 1, 1, 0, 44);
    STEP(5, 1, 1, 1, 53);
    STEP(6, 1, 1, 2, 80);
    STEP(7, 1, 2, 1, 125);
    STEP(8, 1, 2, 2, 170);
    STEP(9, 1, 2, 3, 245);
    REDUCE(3);
#pragma unroll
    for (int o = 0; o < 3; o++) {
        if (vA) atomicAdd(&out[(size_t)aA * FEAT + 16 + m * 3 + o],
                          nnA * outp[leA][o]);
        if (vB) atomicAdd(&out[(size_t)aB * FEAT + 16 + m * 3 + o],
                          nnB * outp[leA + 1][o]);
    }
    CLEAR();

    // ---------------- io = 2 (DOUT = 5, out offset 64) ----------------------
    STEP(10, 2, 0, 2, 350);
    STEP(11, 2, 1, 1, 375);
    STEP(12, 2, 1, 2, 420);
    STEP(13, 2, 1, 3, 495);
    STEP(14, 2, 2, 0, 600);
    STEP(15, 2, 2, 1, 625);
    STEP(16, 2, 2, 2, 700);
    STEP(17, 2, 2, 3, 825);
    STEP(18, 2, 2, 4, 1000);
    REDUCE(5);
#pragma unroll
    for (int o = 0; o < 5; o++) {
        if (vA) atomicAdd(&out[(size_t)aA * FEAT + 64 + m * 5 + o],
                          nnA * outp[leA][o]);
        if (vB) atomicAdd(&out[(size_t)aB * FEAT + 64 + m * 5 + o],
                          nnB * outp[leA + 1][o]);
    }

#undef STEP
#undef REDUCE
#undef CLEAR
#undef ISSUE
#undef COMMITG
}

// ---------------------------------------------------------------------------
extern "C" void kernel_launch(void* const* d_in, const int* in_sizes, int n_in,
                              void* d_out, int out_size)
{
    const float* features = (const float*)d_in[0];
    const float* R        = (const float*)d_in[1];
    const float* Ys       = (const float*)d_in[2];
    const float* radii    = (const float*)d_in[3];
    const float* cg       = (const float*)d_in[4];
    const float* n_norm   = (const float*)d_in[5];
    const int*   map_a    = (const int*)d_in[6];
    const int*   map_b    = (const int*)d_in[7];
    float*       out      = (float*)d_out;

    cudaMemcpyToSymbolAsync(cg_c, cg, 1225 * sizeof(float), 0,
                            cudaMemcpyDeviceToDevice, 0);
    cudaMemsetAsync(out, 0, (size_t)out_size * sizeof(float));

    int grid = (N_EDGES + TILE_E - 1) / TILE_E;   // 7813
    conv_kernel<<<grid, THREADS>>>(features, R, Ys, radii, n_norm,
                                   map_a, map_b, out);
}

// round 6
// speedup vs baseline: 1.0465x; 1.0465x over previous
#include <cuda_runtime.h>
#include <cstdint>

#define N_EDGES 250000
#define N_RBF   10
#define FEAT    144
#define P_TOTAL 4864
#define TILE_E  32
#define THREADS 256
#define VSTRIDE 20                      // Rt w-row stride (16 used + 4 pad)
#define RSLICE  (16 * VSTRIDE)          // 320 floats per r-slice
#define RBUF    (N_RBF * RSLICE)        // 3200 floats per buffer
#define YS_STR  40                      // padded Ys per-edge stride
#define TMP_ESTR 88                     // tmp per-edge stride (conflict-free halves)
#define TMP_WARP (4 * TMP_ESTR)         // 352 floats per warp

__constant__ float cg_c[1225];

// ---------------------------------------------------------------------------
// One path. tmp phase: lane (m,eh) computes tmp[v=m][o] for its 2 edges and
// publishes to warp scratch. W/apply phase: lane handles w=m for ALL 4 warp
// edges but only its v-half (eh); partials combined via shfl.xor(16) at the
// end of each l_out segment.
// ---------------------------------------------------------------------------
template<int IO, int II, int LF, int CGOFF>
__device__ __forceinline__ void do_path(
    const float (&FAr)[9], const float (&FBr)[9],
    const float* __restrict__ Ys_p,     // [TILE_E][YS_STR] padded
    const float* __restrict__ Rt,       // [10][16][VSTRIDE]
    float* __restrict__ tmp_w,          // this warp's scratch
    const float (&rad)[4][N_RBF],
    int m, int eh, int lA, int lB, int leA,
    float (&outp)[4][5])
{
    constexpr int DOUT = 2 * IO + 1;
    constexpr int DI   = 2 * II + 1;
    constexpr int DF   = 2 * LF + 1;
    constexpr int FB0  = (II == 0) ? 0 : ((II == 1) ? 1 : 4);
    constexpr int YB   = (LF == 0) ? 0 : (LF == 1) ? 4 : (LF == 2) ? 12
                       : (LF == 3) ? 20 : 28;
    const float NORM =
        (DF == 1) ? 1.0f :
        (DF == 3) ? 0.57735026918962576f :
        (DF == 5) ? 0.44721359549995794f :
        (DF == 7) ? 0.37796447300922723f :
                    0.33333333333333333f;

    // ---- vectorized Ys loads (padded, 16B aligned blocks) ----
    float yA[DF], yB[DF];
    {
        const float* pa = Ys_p + lA * YS_STR + YB;
        const float* pb = Ys_p + lB * YS_STR + YB;
        if constexpr (DF == 1) {
            yA[0] = pa[0]; yB[0] = pb[0];
        } else if constexpr (DF == 3) {
            float4 qa = *(const float4*)pa, qb = *(const float4*)pb;
            yA[0]=qa.x; yA[1]=qa.y; yA[2]=qa.z;
            yB[0]=qb.x; yB[1]=qb.y; yB[2]=qb.z;
        } else if constexpr (DF == 5) {
            float4 qa = *(const float4*)pa, qb = *(const float4*)pb;
            yA[0]=qa.x; yA[1]=qa.y; yA[2]=qa.z; yA[3]=qa.w; yA[4]=pa[4];
            yB[0]=qb.x; yB[1]=qb.y; yB[2]=qb.z; yB[3]=qb.w; yB[4]=pb[4];
        } else if constexpr (DF == 7) {
            float4 qa0 = *(const float4*)pa, qa1 = *(const float4*)(pa + 4);
            float4 qb0 = *(const float4*)pb, qb1 = *(const float4*)(pb + 4);
            yA[0]=qa0.x; yA[1]=qa0.y; yA[2]=qa0.z; yA[3]=qa0.w;
            yA[4]=qa1.x; yA[5]=qa1.y; yA[6]=qa1.z;
            yB[0]=qb0.x; yB[1]=qb0.y; yB[2]=qb0.z; yB[3]=qb0.w;
            yB[4]=qb1.x; yB[5]=qb1.y; yB[6]=qb1.z;
        } else {
            float4 qa0 = *(const float4*)pa, qa1 = *(const float4*)(pa + 4);
            float4 qb0 = *(const float4*)pb, qb1 = *(const float4*)(pb + 4);
            yA[0]=qa0.x; yA[1]=qa0.y; yA[2]=qa0.z; yA[3]=qa0.w;
            yA[4]=qa1.x; yA[5]=qa1.y; yA[6]=qa1.z; yA[7]=qa1.w; yA[8]=pa[8];
            yB[0]=qb0.x; yB[1]=qb0.y; yB[2]=qb0.z; yB[3]=qb0.w;
            yB[4]=qb1.x; yB[5]=qb1.y; yB[6]=qb1.z; yB[7]=qb1.w; yB[8]=pb[8];
        }
    }

    // ---- tmp[v=m][o] for this lane's 2 edges ----
    float tA[DOUT], tB[DOUT];
#pragma unroll
    for (int o = 0; o < DOUT; o++) { tA[o] = 0.f; tB[o] = 0.f; }

#pragma unroll
    for (int f = 0; f < DF; f++) {
#pragma unroll
        for (int o = 0; o < DOUT; o++) {
            float gA = 0.f, gB = 0.f;
#pragma unroll
            for (int i = 0; i < DI; i++) {
                float c = cg_c[CGOFF + (o * DI + i) * DF + f];  // LDCU uniform
                gA += FAr[FB0 + i] * c;
                gB += FBr[FB0 + i] * c;
            }
            tA[o] += yA[f] * gA;
            tB[o] += yB[f] * gB;
        }
    }

    // ---- publish tmp to warp scratch (conflict-free: stride 88) ----
    __syncwarp();
#pragma unroll
    for (int o = 0; o < DOUT; o++) {
        tmp_w[ leA      * TMP_ESTR + o * 16 + m] = tA[o] * NORM;
        tmp_w[(leA + 1) * TMP_ESTR + o * 16 + m] = tB[o] * NORM;
    }
    __syncwarp();

    // ---- v-split W + apply: lane covers 4 edges, its v-half only ----
    const float* row = Rt + m * VSTRIDE;
#pragma unroll
    for (int g = 0; g < 2; g++) {
        const int v0 = (2 * eh + g) * 4;
        float w4[4][4];
#pragma unroll
        for (int j = 0; j < 4; j++)
#pragma unroll
            for (int k = 0; k < 4; k++) w4[j][k] = 0.f;

#pragma unroll
        for (int r = 0; r < N_RBF; r++) {
            float4 q = *(const float4*)(row + r * RSLICE + v0);
#pragma unroll
            for (int j = 0; j < 4; j++) {
                w4[j][0] += rad[j][r] * q.x;
                w4[j][1] += rad[j][r] * q.y;
                w4[j][2] += rad[j][r] * q.z;
                w4[j][3] += rad[j][r] * q.w;
            }
        }
#pragma unroll
        for (int j = 0; j < 4; j++) {
#pragma unroll
            for (int o = 0; o < DOUT; o++) {
                float4 t = *(const float4*)(tmp_w + j * TMP_ESTR + o * 16 + v0);
                outp[j][o] += w4[j][0] * t.x + w4[j][1] * t.y
                            + w4[j][2] * t.z + w4[j][3] * t.w;
            }
        }
    }
}

// ---------------------------------------------------------------------------
__global__ void __launch_bounds__(THREADS, 2)
conv_kernel(const float* __restrict__ features,
            const float* __restrict__ R,
            const float* __restrict__ Ys,
            const float* __restrict__ radii,
            const float* __restrict__ n_norm,
            const int*   __restrict__ map_a,
            const int*   __restrict__ map_b,
            float* __restrict__ out)
{
    __shared__ __align__(16) float Rt[3][RBUF];          // 38.4 kB (3-stage ring)
    __shared__ __align__(16) float tmp_s[8 * TMP_WARP];  // 11.3 kB
    __shared__ __align__(16) float Ys_p[TILE_E * YS_STR];//  5.1 kB

    const int tid  = threadIdx.x;
    const int warp = tid >> 5;
    const int lane = tid & 31;
    const int m    = lane & 15;
    const int eh   = lane >> 4;
    const int e0   = blockIdx.x * TILE_E;
    const int leA  = eh * 2;
    const int lA   = warp * 4 + leA;
    const int lB   = lA + 1;
    float* tmp_w   = tmp_s + warp * TMP_WARP;

    const uint32_t rt_sm = (uint32_t)__cvta_generic_to_shared(&Rt[0][0]);

    // cp.async.ca staging of path P's R block (2560 floats = 640 16B chunks).
    // .ca keeps R resident in L1 so the co-resident block hits L1.
#define ISSUE(P, BUF)                                                          \
    do {                                                                       \
        uint32_t base = rt_sm + (uint32_t)(BUF) * (RBUF * 4);                  \
        _Pragma("unroll")                                                      \
        for (int c = tid; c < 640; c += THREADS) {                             \
            int k = c >> 6, w = (c >> 2) & 15, q = c & 3;                      \
            const float* src = R + (size_t)k * P_TOTAL + (P) * 256             \
                                 + w * 16 + q * 4;                             \
            uint32_t dst = base + (uint32_t)(((k * 16 + w) * VSTRIDE + q * 4)  \
                                             * 4);                             \
            asm volatile("cp.async.ca.shared.global [%0], [%1], 16;"           \
                         :: "r"(dst), "l"(src));                               \
        }                                                                      \
    } while (0)

#define COMMITG() asm volatile("cp.async.commit_group;" ::: "memory")

    // prologue: two paths in flight
    ISSUE(0, 0); COMMITG();
    ISSUE(1, 1); COMMITG();

    // ---- stage padded Ys ----
    for (int idx = tid; idx < TILE_E * 25; idx += THREADS) {
        int le = idx / 25, f = idx - le * 25;
        int e  = e0 + le;
        int off = (f < 1) ? f : (f < 4) ? 3 + f : (f < 9) ? 8 + f
                : (f < 16) ? 11 + f : 12 + f;
        Ys_p[le * YS_STR + off] = (e < N_EDGES) ? Ys[(size_t)e * 25 + f] : 0.f;
    }

    // ---- per-lane bindings ----
    const int eA = e0 + lA, eB = e0 + lB;
    const bool vA = (eA < N_EDGES), vB = (eB < N_EDGES);
    const int eAc = vA ? eA : 0, eBc = vB ? eB : 0;

    float FAr[9], FBr[9];
    {
        const float* fA = features + (size_t)map_b[eAc] * FEAT;
        const float* fB = features + (size_t)map_b[eBc] * FEAT;
        FAr[0] = fA[m];                 FBr[0] = fB[m];
#pragma unroll
        for (int i = 0; i < 3; i++) { FAr[1 + i] = fA[16 + m * 3 + i];
                                      FBr[1 + i] = fB[16 + m * 3 + i]; }
#pragma unroll
        for (int i = 0; i < 5; i++) { FAr[4 + i] = fA[64 + m * 5 + i];
                                      FBr[4 + i] = fB[64 + m * 5 + i]; }
    }

    // all 4 warp edges' radial coefficients (for v-split W phase)
    float rad[4][N_RBF];
#pragma unroll
    for (int j = 0; j < 4; j++) {
        int e = e0 + warp * 4 + j;
        bool v = (e < N_EDGES);
        int ec = v ? e : 0;
#pragma unroll
        for (int r = 0; r < N_RBF; r++)
            rad[j][r] = v ? radii[(size_t)ec * N_RBF + r] : 0.f;
    }

    const int   aA  = map_a[eAc];
    const int   aB  = map_a[eBc];
    const float nnA = vA ? n_norm[aA] : 0.f;
    const float nnB = vB ? n_norm[aB] : 0.f;

    float outp[4][5];
#pragma unroll
    for (int j = 0; j < 4; j++)
#pragma unroll
        for (int o = 0; o < 5; o++) outp[j][o] = 0.f;

    // STEP P: drain to path P (leave P+1 in flight), sync (also means buffer
    // (P+2)%3 — last read while computing P-1 — is free), issue P+2, compute P.
#define STEP(P, IO, II, LF, CGOFF)                                             \
    do {                                                                       \
        if ((P) < 18)                                                          \
            asm volatile("cp.async.wait_group 1;" ::: "memory");               \
        else                                                                   \
            asm volatile("cp.async.wait_group 0;" ::: "memory");               \
        __syncthreads();                                                       \
        if ((P) < 17) { ISSUE((P) + 2, ((P) + 2) % 3); COMMITG(); }            \
        do_path<IO, II, LF, CGOFF>(FAr, FBr, Ys_p, Rt[(P) % 3], tmp_w,         \
                                   rad, m, eh, lA, lB, leA, outp);             \
    } while (0)

#define REDUCE(DOUT)                                                           \
    do {                                                                       \
        _Pragma("unroll")                                                      \
        for (int j = 0; j < 4; j++)                                            \
            _Pragma("unroll")                                                  \
            for (int o = 0; o < (DOUT); o++)                                   \
                outp[j][o] += __shfl_xor_sync(0xffffffffu, outp[j][o], 16);    \
    } while (0)

#define CLEAR()                                                                \
    do {                                                                       \
        _Pragma("unroll")                                                      \
        for (int j = 0; j < 4; j++)                                            \
            _Pragma("unroll")                                                  \
            for (int o = 0; o < 5; o++) outp[j][o] = 0.f;                      \
    } while (0)

    // ---------------- io = 0 (DOUT = 1, out offset 0) -----------------------
    STEP(0, 0, 0, 0, 0);
    STEP(1, 0, 1, 1, 1);
    STEP(2, 0, 2, 2, 10);
    REDUCE(1);
    if (vA) atomicAdd(&out[(size_t)aA * FEAT + m], nnA * outp[leA][0]);
    if (vB) atomicAdd(&out[(size_t)aB * FEAT + m], nnB * outp[leA + 1][0]);
    CLEAR();

    // ---------------- io = 1 (DOUT = 3, out offset 16) ----------------------
    STEP(3, 1, 0, 1, 35);
    STEP(4, 1, 1, 0, 44);
    STEP(5, 1, 1, 1, 53);
    STEP(6, 1, 1, 2, 80);
    STEP(7, 1, 2, 1, 125);
    STEP(8, 1, 2, 2, 170);
    STEP(9, 1, 2, 3, 245);
    REDUCE(3);
#pragma unroll
    for (int o = 0; o < 3; o++) {
        if (vA) atomicAdd(&out[(size_t)aA * FEAT + 16 + m * 3 + o],
                          nnA * outp[leA][o]);
        if (vB) atomicAdd(&out[(size_t)aB * FEAT + 16 + m * 3 + o],
                          nnB * outp[leA + 1][o]);
    }
    CLEAR();

    // ---------------- io = 2 (DOUT = 5, out offset 64) ----------------------
    STEP(10, 2, 0, 2, 350);
    STEP(11, 2, 1, 1, 375);
    STEP(12, 2, 1, 2, 420);
    STEP(13, 2, 1, 3, 495);
    STEP(14, 2, 2, 0, 600);
    STEP(15, 2, 2, 1, 625);
    STEP(16, 2, 2, 2, 700);
    STEP(17, 2, 2, 3, 825);
    STEP(18, 2, 2, 4, 1000);
    REDUCE(5);
#pragma unroll
    for (int o = 0; o < 5; o++) {
        if (vA) atomicAdd(&out[(size_t)aA * FEAT + 64 + m * 5 + o],
                          nnA * outp[leA][o]);
        if (vB) atomicAdd(&out[(size_t)aB * FEAT + 64 + m * 5 + o],
                          nnB * outp[leA + 1][o]);
    }

#undef STEP
#undef REDUCE
#undef CLEAR
#undef ISSUE
#undef COMMITG
}

// ---------------------------------------------------------------------------
extern "C" void kernel_launch(void* const* d_in, const int* in_sizes, int n_in,
                              void* d_out, int out_size)
{
    const float* features = (const float*)d_in[0];
    const float* R        = (const float*)d_in[1];
    const float* Ys       = (const float*)d_in[2];
    const float* radii    = (const float*)d_in[3];
    const float* cg       = (const float*)d_in[4];
    const float* n_norm   = (const float*)d_in[5];
    const int*   map_a    = (const int*)d_in[6];
    const int*   map_b    = (const int*)d_in[7];
    float*       out      = (float*)d_out;

    cudaMemcpyToSymbolAsync(cg_c, cg, 1225 * sizeof(float), 0,
                            cudaMemcpyDeviceToDevice, 0);
    cudaMemsetAsync(out, 0, (size_t)out_size * sizeof(float));

    int grid = (N_EDGES + TILE_E - 1) / TILE_E;   // 7813
    conv_kernel<<<grid, THREADS>>>(features, R, Ys, radii, n_norm,
                                   map_a, map_b, out);
}

// round 7
// speedup vs baseline: 1.3052x; 1.2472x over previous
#include <cuda_runtime.h>
#include <cstdint>

#define N_EDGES 250000
#define N_RBF   10
#define FEAT    144
#define P_TOTAL 4864
#define TILE_E  32
#define THREADS 256
#define VSTRIDE 20                      // Rt w-row stride (16 used + 4 pad)
#define RSLICE  (16 * VSTRIDE)          // 320 floats per r-slice
#define RBUF    (N_RBF * RSLICE)        // 3200 floats per buffer
#define YS_STR  40                      // padded Ys per-edge stride
#define TMP_ESTR 88                     // tmp per-edge stride
#define TMP_WARP (4 * TMP_ESTR)         // 352 floats per warp
#define RADS_WARP 80                    // per-warp radial table (10 r x 4 j x dup2)

typedef unsigned long long u64;

__constant__ float cg_c[1225];

// ---- packed f32x2 helpers -------------------------------------------------
__device__ __forceinline__ u64 pack2(float lo, float hi) {
    u64 r; asm("mov.b64 %0, {%1,%2};" : "=l"(r) : "f"(lo), "f"(hi)); return r;
}
__device__ __forceinline__ void unpack2(u64 v, float& lo, float& hi) {
    asm("mov.b64 {%0,%1}, %2;" : "=f"(lo), "=f"(hi) : "l"(v));
}
__device__ __forceinline__ u64 ffma2(u64 a, u64 b, u64 c) {
    u64 d; asm("fma.rn.f32x2 %0, %1, %2, %3;" : "=l"(d) : "l"(a), "l"(b), "l"(c));
    return d;
}
__device__ __forceinline__ u64 fmul2(u64 a, u64 b) {
    u64 d; asm("mul.rn.f32x2 %0, %1, %2;" : "=l"(d) : "l"(a), "l"(b)); return d;
}
__device__ __forceinline__ u64 fadd2(u64 a, u64 b) {
    u64 d; asm("add.rn.f32x2 %0, %1, %2;" : "=l"(d) : "l"(a), "l"(b)); return d;
}

// ---------------------------------------------------------------------------
// One path, f32x2-packed.
// tmp phase: packed over the lane's (A,B) edge pair; published to warp scratch
// as scalars. W/apply: packed over v-pairs; lane covers all 4 warp edges but
// only its eh v-half; packed partials land in acc[4][5] (lo+hi+shfl folded at
// segment end).
// ---------------------------------------------------------------------------
template<int IO, int II, int LF, int CGOFF>
__device__ __forceinline__ void do_path(
    const u64 (&FAB)[9],
    const float* __restrict__ Ys_p,     // [TILE_E][YS_STR] padded
    const float* __restrict__ Rt,       // [10][16][VSTRIDE]
    float* __restrict__ tmp_w,          // this warp's tmp scratch
    const float* __restrict__ radS_w,   // this warp's dup'd radial table
    int m, int eh, int lA, int lB, int leA,
    u64 (&acc)[4][5])
{
    constexpr int DOUT = 2 * IO + 1;
    constexpr int DI   = 2 * II + 1;
    constexpr int DF   = 2 * LF + 1;
    constexpr int FB0  = (II == 0) ? 0 : ((II == 1) ? 1 : 4);
    constexpr int YB   = (LF == 0) ? 0 : (LF == 1) ? 4 : (LF == 2) ? 12
                       : (LF == 3) ? 20 : 28;
    const float NORM =
        (DF == 1) ? 1.0f :
        (DF == 3) ? 0.57735026918962576f :
        (DF == 5) ? 0.44721359549995794f :
        (DF == 7) ? 0.37796447300922723f :
                    0.33333333333333333f;

    // ---- packed Ys (vector loads, then A/B pack) ----
    u64 yAB[DF];
    {
        float ya[DF], yb[DF];
        const float* pa = Ys_p + lA * YS_STR + YB;
        const float* pb = Ys_p + lB * YS_STR + YB;
#pragma unroll
        for (int f4 = 0; f4 < DF / 4; f4++) {
            float4 qa = *(const float4*)(pa + 4 * f4);
            float4 qb = *(const float4*)(pb + 4 * f4);
            ya[4*f4+0]=qa.x; ya[4*f4+1]=qa.y; ya[4*f4+2]=qa.z; ya[4*f4+3]=qa.w;
            yb[4*f4+0]=qb.x; yb[4*f4+1]=qb.y; yb[4*f4+2]=qb.z; yb[4*f4+3]=qb.w;
        }
#pragma unroll
        for (int f = (DF / 4) * 4; f < DF; f++) { ya[f] = pa[f]; yb[f] = pb[f]; }
#pragma unroll
        for (int f = 0; f < DF; f++) yAB[f] = pack2(ya[f], yb[f]);
    }

    // ---- packed tmp[v=m][o] for the (A,B) pair ----
    u64 tAB[DOUT];
#pragma unroll
    for (int o = 0; o < DOUT; o++) tAB[o] = 0ull;

#pragma unroll
    for (int f = 0; f < DF; f++) {
#pragma unroll
        for (int o = 0; o < DOUT; o++) {
            float c0 = cg_c[CGOFF + (o * DI + 0) * DF + f];   // ULDCU uniform
            u64 g = fmul2(FAB[FB0], pack2(c0, c0));
#pragma unroll
            for (int i = 1; i < DI; i++) {
                float c = cg_c[CGOFF + (o * DI + i) * DF + f];
                g = ffma2(FAB[FB0 + i], pack2(c, c), g);
            }
            tAB[o] = ffma2(yAB[f], g, tAB[o]);
        }
    }
    {
        u64 nrm = pack2(NORM, NORM);
#pragma unroll
        for (int o = 0; o < DOUT; o++) tAB[o] = fmul2(tAB[o], nrm);
    }

    // ---- publish tmp scalars to warp scratch ----
    __syncwarp();
#pragma unroll
    for (int o = 0; o < DOUT; o++) {
        float lo, hi; unpack2(tAB[o], lo, hi);
        tmp_w[ leA      * TMP_ESTR + o * 16 + m] = lo;
        tmp_w[(leA + 1) * TMP_ESTR + o * 16 + m] = hi;
    }
    __syncwarp();

    // ---- W (packed over v-pairs) + apply ----
    const float* row = Rt + m * VSTRIDE;
#pragma unroll
    for (int g = 0; g < 2; g++) {
        const int v0 = eh * 8 + g * 4;
        u64 wP[4][2];
#pragma unroll
        for (int j = 0; j < 4; j++) { wP[j][0] = 0ull; wP[j][1] = 0ull; }

#pragma unroll
        for (int r = 0; r < N_RBF; r++) {
            float4 qf = *(const float4*)(row + r * RSLICE + v0);
            u64 q01, q23;
            q01 = pack2(qf.x, qf.y); q23 = pack2(qf.z, qf.w);
            // dup'd radials: [r][8] = (d0,d0,d1,d1,d2,d2,d3,d3)
            float4 rd0 = *(const float4*)(radS_w + r * 8);
            float4 rd1 = *(const float4*)(radS_w + r * 8 + 4);
            u64 d0 = pack2(rd0.x, rd0.y);
            u64 d1 = pack2(rd0.z, rd0.w);
            u64 d2 = pack2(rd1.x, rd1.y);
            u64 d3 = pack2(rd1.z, rd1.w);
            wP[0][0] = ffma2(d0, q01, wP[0][0]); wP[0][1] = ffma2(d0, q23, wP[0][1]);
            wP[1][0] = ffma2(d1, q01, wP[1][0]); wP[1][1] = ffma2(d1, q23, wP[1][1]);
            wP[2][0] = ffma2(d2, q01, wP[2][0]); wP[2][1] = ffma2(d2, q23, wP[2][1]);
            wP[3][0] = ffma2(d3, q01, wP[3][0]); wP[3][1] = ffma2(d3, q23, wP[3][1]);
        }
#pragma unroll
        for (int j = 0; j < 4; j++) {
#pragma unroll
            for (int o = 0; o < DOUT; o++) {
                float4 tf = *(const float4*)(tmp_w + j * TMP_ESTR + o * 16 + v0);
                u64 t01 = pack2(tf.x, tf.y), t23 = pack2(tf.z, tf.w);
                acc[j][o] = ffma2(wP[j][0], t01, acc[j][o]);
                acc[j][o] = ffma2(wP[j][1], t23, acc[j][o]);
            }
        }
    }
}

// ---------------------------------------------------------------------------
__global__ void __launch_bounds__(THREADS, 2)
conv_kernel(const float* __restrict__ features,
            const float* __restrict__ R,
            const float* __restrict__ Ys,
            const float* __restrict__ radii,
            const float* __restrict__ n_norm,
            const int*   __restrict__ map_a,
            const int*   __restrict__ map_b,
            float* __restrict__ out)
{
    __shared__ __align__(16) float Rt[3][RBUF];           // 38.4 kB
    __shared__ __align__(16) float tmp_s[8 * TMP_WARP];   // 11.3 kB
    __shared__ __align__(16) float Ys_p[TILE_E * YS_STR]; //  5.1 kB
    __shared__ __align__(16) float radS[8 * RADS_WARP];   //  2.6 kB

    const int tid  = threadIdx.x;
    const int warp = tid >> 5;
    const int lane = tid & 31;
    const int m    = lane & 15;
    const int eh   = lane >> 4;
    const int e0   = blockIdx.x * TILE_E;
    const int leA  = eh * 2;
    const int lA   = warp * 4 + leA;
    const int lB   = lA + 1;
    float* tmp_w   = tmp_s + warp * TMP_WARP;
    const float* radS_w = radS + warp * RADS_WARP;

    const uint32_t rt_sm = (uint32_t)__cvta_generic_to_shared(&Rt[0][0]);

#define ISSUE(P, BUF)                                                          \
    do {                                                                       \
        uint32_t base = rt_sm + (uint32_t)(BUF) * (RBUF * 4);                  \
        _Pragma("unroll")                                                      \
        for (int c = tid; c < 640; c += THREADS) {                             \
            int k = c >> 6, w = (c >> 2) & 15, q = c & 3;                      \
            const float* src = R + (size_t)k * P_TOTAL + (P) * 256             \
                                 + w * 16 + q * 4;                             \
            uint32_t dst = base + (uint32_t)(((k * 16 + w) * VSTRIDE + q * 4)  \
                                             * 4);                             \
            asm volatile("cp.async.ca.shared.global [%0], [%1], 16;"           \
                         :: "r"(dst), "l"(src));                               \
        }                                                                      \
    } while (0)

#define COMMITG() asm volatile("cp.async.commit_group;" ::: "memory")

    ISSUE(0, 0); COMMITG();
    ISSUE(1, 1); COMMITG();

    // ---- stage padded Ys ----
    for (int idx = tid; idx < TILE_E * 25; idx += THREADS) {
        int le = idx / 25, f = idx - le * 25;
        int e  = e0 + le;
        int off = (f < 1) ? f : (f < 4) ? 3 + f : (f < 9) ? 8 + f
                : (f < 16) ? 11 + f : 12 + f;
        Ys_p[le * YS_STR + off] = (e < N_EDGES) ? Ys[(size_t)e * 25 + f] : 0.f;
    }

    // ---- per-warp duplicated radial table: radS[warp][r][2j+d] ----
    for (int idx = lane; idx < RADS_WARP; idx += 32) {
        int r = idx >> 3, j = (idx & 7) >> 1;
        int e = e0 + warp * 4 + j;
        bool v = (e < N_EDGES);
        radS[warp * RADS_WARP + idx] =
            v ? radii[(size_t)(v ? e : 0) * N_RBF + r] : 0.f;
    }

    // ---- per-lane bindings ----
    const int eA = e0 + lA, eB = e0 + lB;
    const bool vA = (eA < N_EDGES), vB = (eB < N_EDGES);
    const int eAc = vA ? eA : 0, eBc = vB ? eB : 0;

    u64 FAB[9];
    {
        const float* fA = features + (size_t)map_b[eAc] * FEAT;
        const float* fB = features + (size_t)map_b[eBc] * FEAT;
        FAB[0] = pack2(fA[m], fB[m]);
#pragma unroll
        for (int i = 0; i < 3; i++)
            FAB[1 + i] = pack2(fA[16 + m * 3 + i], fB[16 + m * 3 + i]);
#pragma unroll
        for (int i = 0; i < 5; i++)
            FAB[4 + i] = pack2(fA[64 + m * 5 + i], fB[64 + m * 5 + i]);
    }

    const int   aA  = map_a[eAc];
    const int   aB  = map_a[eBc];
    const float nnA = vA ? n_norm[aA] : 0.f;
    const float nnB = vB ? n_norm[aB] : 0.f;

    u64 acc[4][5];
#pragma unroll
    for (int j = 0; j < 4; j++)
#pragma unroll
        for (int o = 0; o < 5; o++) acc[j][o] = 0ull;

    __syncthreads();   // Ys_p, radS visible

#define STEP(P, IO, II, LF, CGOFF)                                             \
    do {                                                                       \
        if ((P) < 18)                                                          \
            asm volatile("cp.async.wait_group 1;" ::: "memory");               \
        else                                                                   \
            asm volatile("cp.async.wait_group 0;" ::: "memory");               \
        __syncthreads();                                                       \
        if ((P) < 17) { ISSUE((P) + 2, ((P) + 2) % 3); COMMITG(); }            \
        do_path<IO, II, LF, CGOFF>(FAB, Ys_p, Rt[(P) % 3], tmp_w, radS_w,      \
                                   m, eh, lA, lB, leA, acc);                   \
    } while (0)

    // fold packed partials: cross-half shfl, then lo+hi
#define EMIT(DOUT, EXPR_IDX)                                                   \
    do {                                                                       \
        float tot[4][DOUT];                                                    \
        _Pragma("unroll")                                                      \
        for (int j = 0; j < 4; j++)                                            \
            _Pragma("unroll")                                                  \
            for (int o = 0; o < (DOUT); o++) {                                 \
                u64 s = fadd2(acc[j][o],                                       \
                              __shfl_xor_sync(0xffffffffu, acc[j][o], 16));    \
                float lo, hi; unpack2(s, lo, hi);                              \
                tot[j][o] = lo + hi;                                           \
            }                                                                  \
        _Pragma("unroll")                                                      \
        for (int o = 0; o < (DOUT); o++) {                                     \
            if (vA) atomicAdd(&out[(size_t)aA * FEAT + (EXPR_IDX)],            \
                              nnA * tot[leA][o]);                              \
            if (vB) atomicAdd(&out[(size_t)aB * FEAT + (EXPR_IDX)],            \
                              nnB * tot[leA + 1][o]);                          \
        }                                                                      \
    } while (0)

#define CLEAR()                                                                \
    do {                                                                       \
        _Pragma("unroll")                                                      \
        for (int j = 0; j < 4; j++)                                            \
            _Pragma("unroll")                                                  \
            for (int o = 0; o < 5; o++) acc[j][o] = 0ull;                      \
    } while (0)

    // ---------------- io = 0 (DOUT = 1, out offset 0) -----------------------
    STEP(0, 0, 0, 0, 0);
    STEP(1, 0, 1, 1, 1);
    STEP(2, 0, 2, 2, 10);
    EMIT(1, m);
    CLEAR();

    // ---------------- io = 1 (DOUT = 3, out offset 16) ----------------------
    STEP(3, 1, 0, 1, 35);
    STEP(4, 1, 1, 0, 44);
    STEP(5, 1, 1, 1, 53);
    STEP(6, 1, 1, 2, 80);
    STEP(7, 1, 2, 1, 125);
    STEP(8, 1, 2, 2, 170);
    STEP(9, 1, 2, 3, 245);
    EMIT(3, 16 + m * 3 + o);
    CLEAR();

    // ---------------- io = 2 (DOUT = 5, out offset 64) ----------------------
    STEP(10, 2, 0, 2, 350);
    STEP(11, 2, 1, 1, 375);
    STEP(12, 2, 1, 2, 420);
    STEP(13, 2, 1, 3, 495);
    STEP(14, 2, 2, 0, 600);
    STEP(15, 2, 2, 1, 625);
    STEP(16, 2, 2, 2, 700);
    STEP(17, 2, 2, 3, 825);
    STEP(18, 2, 2, 4, 1000);
    EMIT(5, 64 + m * 5 + o);

#undef STEP
#undef EMIT
#undef CLEAR
#undef ISSUE
#undef COMMITG
}

// ---------------------------------------------------------------------------
extern "C" void kernel_launch(void* const* d_in, const int* in_sizes, int n_in,
                              void* d_out, int out_size)
{
    const float* features = (const float*)d_in[0];
    const float* R        = (const float*)d_in[1];
    const float* Ys       = (const float*)d_in[2];
    const float* radii    = (const float*)d_in[3];
    const float* cg       = (const float*)d_in[4];
    const float* n_norm   = (const float*)d_in[5];
    const int*   map_a    = (const int*)d_in[6];
    const int*   map_b    = (const int*)d_in[7];
    float*       out      = (float*)d_out;

    cudaMemcpyToSymbolAsync(cg_c, cg, 1225 * sizeof(float), 0,
                            cudaMemcpyDeviceToDevice, 0);
    cudaMemsetAsync(out, 0, (size_t)out_size * sizeof(float));

    int grid = (N_EDGES + TILE_E - 1) / TILE_E;   // 7813
    conv_kernel<<<grid, THREADS>>>(features, R, Ys, radii, n_norm,
                                   map_a, map_b, out);
}

// round 8
// speedup vs baseline: 1.3396x; 1.0264x over previous
#include <cuda_runtime.h>
#include <cstdint>

#define N_EDGES 250000
#define N_RBF   10
#define FEAT    144
#define P_TOTAL 4864
#define TILE_E  32
#define THREADS 256
#define VSTRIDE 20                      // Rt w-row stride (16 used + 4 pad)
#define RSLICE  (16 * VSTRIDE)          // 320 floats per r-slice
#define RBUF    (N_RBF * RSLICE)        // 3200 floats per path slice/buffer
#define YS_STR  40                      // padded Ys per-edge stride
#define TMP_ESTR 88                     // tmp per-edge stride
#define TMP_WARP (4 * TMP_ESTR)         // 352 floats per warp
#define RADS_WARP 80                    // per-warp radial table (10 r x 4 j x dup2)
#define NPATH   19

typedef unsigned long long u64;

__constant__ float cg_c[1225];
__device__ float R_pad[NPATH * RBUF];   // padded+transposed+norm-folded R (243 kB)

// ---- packed f32x2 helpers -------------------------------------------------
__device__ __forceinline__ u64 pack2(float lo, float hi) {
    u64 r; asm("mov.b64 %0, {%1,%2};" : "=l"(r) : "f"(lo), "f"(hi)); return r;
}
__device__ __forceinline__ void unpack2(u64 v, float& lo, float& hi) {
    asm("mov.b64 {%0,%1}, %2;" : "=f"(lo), "=f"(hi) : "l"(v));
}
__device__ __forceinline__ u64 ffma2(u64 a, u64 b, u64 c) {
    u64 d; asm("fma.rn.f32x2 %0, %1, %2, %3;" : "=l"(d) : "l"(a), "l"(b), "l"(c));
    return d;
}
__device__ __forceinline__ u64 fmul2(u64 a, u64 b) {
    u64 d; asm("mul.rn.f32x2 %0, %1, %2;" : "=l"(d) : "l"(a), "l"(b)); return d;
}
__device__ __forceinline__ u64 fadd2(u64 a, u64 b) {
    u64 d; asm("add.rn.f32x2 %0, %1, %2;" : "=l"(d) : "l"(a), "l"(b)); return d;
}

// ---------------------------------------------------------------------------
// Prep: relayout R into R_pad[p][r][w*VSTRIDE + v] with 1/sqrt(df) folded in.
// ---------------------------------------------------------------------------
__global__ void prep_kernel(const float* __restrict__ R)
{
    const float norms[NPATH] = {
        1.0f, 0.57735026918962576f, 0.44721359549995794f,              // io=0
        0.57735026918962576f, 1.0f, 0.57735026918962576f,
        0.44721359549995794f, 0.57735026918962576f,
        0.44721359549995794f, 0.37796447300922723f,                    // io=1
        0.44721359549995794f, 0.57735026918962576f,
        0.44721359549995794f, 0.37796447300922723f, 1.0f,
        0.57735026918962576f, 0.44721359549995794f,
        0.37796447300922723f, 0.33333333333333333f                     // io=2
    };
    int idx = blockIdx.x * blockDim.x + threadIdx.x;
    if (idx >= NPATH * RBUF) return;
    int p    = idx / RBUF,   rem  = idx - p * RBUF;
    int r    = rem / RSLICE; int rem2 = rem - r * RSLICE;
    int w    = rem2 / VSTRIDE, v = rem2 - w * VSTRIDE;
    float val = 0.f;
    if (v < 16)
        val = R[(size_t)r * P_TOTAL + p * 256 + w * 16 + v] * norms[p];
    R_pad[idx] = val;
}

// ---------------------------------------------------------------------------
// One path, f32x2-packed. tmp phase packed over the lane's (A,B) edge pair;
// W/apply phase: v-split across halves, r-outer loop with radS loads hoisted
// (each rd pair serves both v-quads). Norm is pre-folded into R_pad.
// ---------------------------------------------------------------------------
template<int IO, int II, int LF, int CGOFF>
__device__ __forceinline__ void do_path(
    const u64 (&FAB)[9],
    const float* __restrict__ Ys_p,     // [TILE_E][YS_STR] padded
    const float* __restrict__ Rt,       // [10][16][VSTRIDE]
    float* __restrict__ tmp_w,          // this warp's tmp scratch
    const float* __restrict__ radS_w,   // this warp's dup'd radial table
    int m, int eh, int lA, int lB, int leA,
    u64 (&acc)[4][5])
{
    constexpr int DOUT = 2 * IO + 1;
    constexpr int DI   = 2 * II + 1;
    constexpr int DF   = 2 * LF + 1;
    constexpr int FB0  = (II == 0) ? 0 : ((II == 1) ? 1 : 4);
    constexpr int YB   = (LF == 0) ? 0 : (LF == 1) ? 4 : (LF == 2) ? 12
                       : (LF == 3) ? 20 : 28;

    // ---- packed Ys ----
    u64 yAB[DF];
    {
        float ya[DF], yb[DF];
        const float* pa = Ys_p + lA * YS_STR + YB;
        const float* pb = Ys_p + lB * YS_STR + YB;
#pragma unroll
        for (int f4 = 0; f4 < DF / 4; f4++) {
            float4 qa = *(const float4*)(pa + 4 * f4);
            float4 qb = *(const float4*)(pb + 4 * f4);
            ya[4*f4+0]=qa.x; ya[4*f4+1]=qa.y; ya[4*f4+2]=qa.z; ya[4*f4+3]=qa.w;
            yb[4*f4+0]=qb.x; yb[4*f4+1]=qb.y; yb[4*f4+2]=qb.z; yb[4*f4+3]=qb.w;
        }
#pragma unroll
        for (int f = (DF / 4) * 4; f < DF; f++) { ya[f] = pa[f]; yb[f] = pb[f]; }
#pragma unroll
        for (int f = 0; f < DF; f++) yAB[f] = pack2(ya[f], yb[f]);
    }

    // ---- packed tmp[v=m][o] for the (A,B) pair ----
    u64 tAB[DOUT];
#pragma unroll
    for (int o = 0; o < DOUT; o++) tAB[o] = 0ull;

#pragma unroll
    for (int f = 0; f < DF; f++) {
#pragma unroll
        for (int o = 0; o < DOUT; o++) {
            float c0 = cg_c[CGOFF + (o * DI + 0) * DF + f];   // LDCU uniform
            u64 g = fmul2(FAB[FB0], pack2(c0, c0));
#pragma unroll
            for (int i = 1; i < DI; i++) {
                float c = cg_c[CGOFF + (o * DI + i) * DF + f];
                g = ffma2(FAB[FB0 + i], pack2(c, c), g);
            }
            tAB[o] = ffma2(yAB[f], g, tAB[o]);
        }
    }

    // ---- publish tmp scalars to warp scratch ----
    __syncwarp();
#pragma unroll
    for (int o = 0; o < DOUT; o++) {
        float lo, hi; unpack2(tAB[o], lo, hi);
        tmp_w[ leA      * TMP_ESTR + o * 16 + m] = lo;
        tmp_w[(leA + 1) * TMP_ESTR + o * 16 + m] = hi;
    }
    __syncwarp();

    // ---- W: r-outer, radS loads hoisted across both v-quads ----
    const float* row = Rt + m * VSTRIDE + eh * 8;
    u64 wP[4][2][2];   // [edge j][quad g][v-pair]
#pragma unroll
    for (int j = 0; j < 4; j++)
#pragma unroll
        for (int g = 0; g < 2; g++) { wP[j][g][0] = 0ull; wP[j][g][1] = 0ull; }

#pragma unroll
    for (int r = 0; r < N_RBF; r++) {
        float4 rd0 = *(const float4*)(radS_w + r * 8);      // (d0,d0',d1,d1')
        float4 rd1 = *(const float4*)(radS_w + r * 8 + 4);  // (d2,d2',d3,d3')
        u64 d0 = pack2(rd0.x, rd0.y);
        u64 d1 = pack2(rd0.z, rd0.w);
        u64 d2 = pack2(rd1.x, rd1.y);
        u64 d3 = pack2(rd1.z, rd1.w);
        float4 q0 = *(const float4*)(row + r * RSLICE);       // quad g=0
        float4 q1 = *(const float4*)(row + r * RSLICE + 4);   // quad g=1
        u64 q00 = pack2(q0.x, q0.y), q01 = pack2(q0.z, q0.w);
        u64 q10 = pack2(q1.x, q1.y), q11 = pack2(q1.z, q1.w);
        wP[0][0][0] = ffma2(d0, q00, wP[0][0][0]);
        wP[0][0][1] = ffma2(d0, q01, wP[0][0][1]);
        wP[0][1][0] = ffma2(d0, q10, wP[0][1][0]);
        wP[0][1][1] = ffma2(d0, q11, wP[0][1][1]);
        wP[1][0][0] = ffma2(d1, q00, wP[1][0][0]);
        wP[1][0][1] = ffma2(d1, q01, wP[1][0][1]);
        wP[1][1][0] = ffma2(d1, q10, wP[1][1][0]);
        wP[1][1][1] = ffma2(d1, q11, wP[1][1][1]);
        wP[2][0][0] = ffma2(d2, q00, wP[2][0][0]);
        wP[2][0][1] = ffma2(d2, q01, wP[2][0][1]);
        wP[2][1][0] = ffma2(d2, q10, wP[2][1][0]);
        wP[2][1][1] = ffma2(d2, q11, wP[2][1][1]);
        wP[3][0][0] = ffma2(d3, q00, wP[3][0][0]);
        wP[3][0][1] = ffma2(d3, q01, wP[3][0][1]);
        wP[3][1][0] = ffma2(d3, q10, wP[3][1][0]);
        wP[3][1][1] = ffma2(d3, q11, wP[3][1][1]);
    }

    // ---- apply ----
#pragma unroll
    for (int g = 0; g < 2; g++) {
        const int v0 = eh * 8 + g * 4;
#pragma unroll
        for (int j = 0; j < 4; j++) {
#pragma unroll
            for (int o = 0; o < DOUT; o++) {
                float4 tf = *(const float4*)(tmp_w + j * TMP_ESTR + o * 16 + v0);
                u64 t01 = pack2(tf.x, tf.y), t23 = pack2(tf.z, tf.w);
                acc[j][o] = ffma2(wP[j][g][0], t01, acc[j][o]);
                acc[j][o] = ffma2(wP[j][g][1], t23, acc[j][o]);
            }
        }
    }
}

// ---------------------------------------------------------------------------
__global__ void __launch_bounds__(THREADS, 2)
conv_kernel(const float* __restrict__ features,
            const float* __restrict__ Ys,
            const float* __restrict__ radii,
            const float* __restrict__ n_norm,
            const int*   __restrict__ map_a,
            const int*   __restrict__ map_b,
            float* __restrict__ out)
{
    __shared__ __align__(16) float Rt[3][RBUF];           // 38.4 kB
    __shared__ __align__(16) float tmp_s[8 * TMP_WARP];   // 11.3 kB
    __shared__ __align__(16) float Ys_p[TILE_E * YS_STR]; //  5.1 kB
    __shared__ __align__(16) float radS[8 * RADS_WARP];   //  2.6 kB

    const int tid  = threadIdx.x;
    const int warp = tid >> 5;
    const int lane = tid & 31;
    const int m    = lane & 15;
    const int eh   = lane >> 4;
    const int e0   = blockIdx.x * TILE_E;
    const int leA  = eh * 2;
    const int lA   = warp * 4 + leA;
    const int lB   = lA + 1;
    float* tmp_w   = tmp_s + warp * TMP_WARP;
    const float* radS_w = radS + warp * RADS_WARP;

    const uint32_t rt_sm = (uint32_t)__cvta_generic_to_shared(&Rt[0][0]);

    // linear cp.async staging from pre-laid-out R_pad (800 x 16B per path)
#define ISSUE(P, BUF)                                                          \
    do {                                                                       \
        uint32_t base = rt_sm + (uint32_t)(BUF) * (RBUF * 4);                  \
        const float* src0 = R_pad + (size_t)(P) * RBUF;                        \
        _Pragma("unroll")                                                      \
        for (int c = tid; c < RBUF / 4; c += THREADS) {                        \
            asm volatile("cp.async.ca.shared.global [%0], [%1], 16;"           \
                         :: "r"(base + (uint32_t)(c * 16)), "l"(src0 + c * 4));\
        }                                                                      \
    } while (0)

#define COMMITG() asm volatile("cp.async.commit_group;" ::: "memory")

    ISSUE(0, 0); COMMITG();
    ISSUE(1, 1); COMMITG();

    // ---- stage padded Ys ----
    for (int idx = tid; idx < TILE_E * 25; idx += THREADS) {
        int le = idx / 25, f = idx - le * 25;
        int e  = e0 + le;
        int off = (f < 1) ? f : (f < 4) ? 3 + f : (f < 9) ? 8 + f
                : (f < 16) ? 11 + f : 12 + f;
        Ys_p[le * YS_STR + off] = (e < N_EDGES) ? Ys[(size_t)e * 25 + f] : 0.f;
    }

    // ---- per-warp duplicated radial table: radS[warp][r][2j+d] ----
    for (int idx = lane; idx < RADS_WARP; idx += 32) {
        int r = idx >> 3, j = (idx & 7) >> 1;
        int e = e0 + warp * 4 + j;
        bool v = (e < N_EDGES);
        radS[warp * RADS_WARP + idx] =
            v ? radii[(size_t)(v ? e : 0) * N_RBF + r] : 0.f;
    }

    // ---- per-lane bindings ----
    const int eA = e0 + lA, eB = e0 + lB;
    const bool vA = (eA < N_EDGES), vB = (eB < N_EDGES);
    const int eAc = vA ? eA : 0, eBc = vB ? eB : 0;

    u64 FAB[9];
    {
        const float* fA = features + (size_t)map_b[eAc] * FEAT;
        const float* fB = features + (size_t)map_b[eBc] * FEAT;
        FAB[0] = pack2(fA[m], fB[m]);
#pragma unroll
        for (int i = 0; i < 3; i++)
            FAB[1 + i] = pack2(fA[16 + m * 3 + i], fB[16 + m * 3 + i]);
#pragma unroll
        for (int i = 0; i < 5; i++)
            FAB[4 + i] = pack2(fA[64 + m * 5 + i], fB[64 + m * 5 + i]);
    }

    const int   aA  = map_a[eAc];
    const int   aB  = map_a[eBc];
    const float nnA = vA ? n_norm[aA] : 0.f;
    const float nnB = vB ? n_norm[aB] : 0.f;

    u64 acc[4][5];
#pragma unroll
    for (int j = 0; j < 4; j++)
#pragma unroll
        for (int o = 0; o < 5; o++) acc[j][o] = 0ull;

    __syncthreads();   // Ys_p, radS visible

#define STEP(P, IO, II, LF, CGOFF)                                             \
    do {                                                                       \
        if ((P) < 18)                                                          \
            asm volatile("cp.async.wait_group 1;" ::: "memory");               \
        else                                                                   \
            asm volatile("cp.async.wait_group 0;" ::: "memory");               \
        __syncthreads();                                                       \
        if ((P) < 17) { ISSUE((P) + 2, ((P) + 2) % 3); COMMITG(); }            \
        do_path<IO, II, LF, CGOFF>(FAB, Ys_p, Rt[(P) % 3], tmp_w, radS_w,      \
                                   m, eh, lA, lB, leA, acc);                   \
    } while (0)

#define EMIT(DOUT, EXPR_IDX)                                                   \
    do {                                                                       \
        float tot[4][DOUT];                                                    \
        _Pragma("unroll")                                                      \
        for (int j = 0; j < 4; j++)                                            \
            _Pragma("unroll")                                                  \
            for (int o = 0; o < (DOUT); o++) {                                 \
                u64 s = fadd2(acc[j][o],                                       \
                              __shfl_xor_sync(0xffffffffu, acc[j][o], 16));    \
                float lo, hi; unpack2(s, lo, hi);                              \
                tot[j][o] = lo + hi;                                           \
            }                                                                  \
        _Pragma("unroll")                                                      \
        for (int o = 0; o < (DOUT); o++) {                                     \
            if (vA) atomicAdd(&out[(size_t)aA * FEAT + (EXPR_IDX)],            \
                              nnA * tot[leA][o]);                              \
            if (vB) atomicAdd(&out[(size_t)aB * FEAT + (EXPR_IDX)],            \
                              nnB * tot[leA + 1][o]);                          \
        }                                                                      \
    } while (0)

#define CLEAR()                                                                \
    do {                                                                       \
        _Pragma("unroll")                                                      \
        for (int j = 0; j < 4; j++)                                            \
            _Pragma("unroll")                                                  \
            for (int o = 0; o < 5; o++) acc[j][o] = 0ull;                      \
    } while (0)

    // ---------------- io = 0 (DOUT = 1, out offset 0) -----------------------
    STEP(0, 0, 0, 0, 0);
    STEP(1, 0, 1, 1, 1);
    STEP(2, 0, 2, 2, 10);
    EMIT(1, m);
    CLEAR();

    // ---------------- io = 1 (DOUT = 3, out offset 16) ----------------------
    STEP(3, 1, 0, 1, 35);
    STEP(4, 1, 1, 0, 44);
    STEP(5, 1, 1, 1, 53);
    STEP(6, 1, 1, 2, 80);
    STEP(7, 1, 2, 1, 125);
    STEP(8, 1, 2, 2, 170);
    STEP(9, 1, 2, 3, 245);
    EMIT(3, 16 + m * 3 + o);
    CLEAR();

    // ---------------- io = 2 (DOUT = 5, out offset 64) ----------------------
    STEP(10, 2, 0, 2, 350);
    STEP(11, 2, 1, 1, 375);
    STEP(12, 2, 1, 2, 420);
    STEP(13, 2, 1, 3, 495);
    STEP(14, 2, 2, 0, 600);
    STEP(15, 2, 2, 1, 625);
    STEP(16, 2, 2, 2, 700);
    STEP(17, 2, 2, 3, 825);
    STEP(18, 2, 2, 4, 1000);
    EMIT(5, 64 + m * 5 + o);

#undef STEP
#undef EMIT
#undef CLEAR
#undef ISSUE
#undef COMMITG
}

// ---------------------------------------------------------------------------
extern "C" void kernel_launch(void* const* d_in, const int* in_sizes, int n_in,
                              void* d_out, int out_size)
{
    const float* features = (const float*)d_in[0];
    const float* R        = (const float*)d_in[1];
    const float* Ys       = (const float*)d_in[2];
    const float* radii    = (const float*)d_in[3];
    const float* cg       = (const float*)d_in[4];
    const float* n_norm   = (const float*)d_in[5];
    const int*   map_a    = (const int*)d_in[6];
    const int*   map_b    = (const int*)d_in[7];
    float*       out      = (float*)d_out;

    cudaMemcpyToSymbolAsync(cg_c, cg, 1225 * sizeof(float), 0,
                            cudaMemcpyDeviceToDevice, 0);
    cudaMemsetAsync(out, 0, (size_t)out_size * sizeof(float));

    prep_kernel<<<(NPATH * RBUF + 255) / 256, 256>>>(R);

    int grid = (N_EDGES + TILE_E - 1) / TILE_E;   // 7813
    conv_kernel<<<grid, THREADS>>>(features, Ys, radii, n_norm,
                                   map_a, map_b, out);
}